// round 1
// baseline (speedup 1.0000x reference)
#include <cuda_runtime.h>
#include <cuda_bf16.h>

// Soft decision tree forward, fused single kernel.
// Only chain nodes {0,1,3,7,15,31} of the 63 inner nodes are used by the
// reference -> 10.5x work reduction vs naive.
//
// GEMM1: H[64 x 384] = relu(X[64x128] @ W1cat[128x384] + b1cat)   (per CTA tile)
// probs: p[64 x 6]   = sigmoid(per-node 64-dot of H with W2 + b2)
// out:   6-level pairwise fold of leaf[64] with p (126 FMA/sample)

#define BM      64      // samples per CTA
#define KDIM    128     // input dim
#define NCOLS   384     // 6 nodes * 64 hidden
#define THREADS 384     // 48 x 8 thread grid
#define KC      16      // k-chunk staged in smem

__device__ __constant__ int NODE_IDS[6] = {0, 1, 3, 7, 15, 31};

// smem layout (floats):
//  Xs    [BM][KDIM]          8192
//  Bs    [KC][NCOLS]         6144
//  b1s   [NCOLS]              384
//  W2s   [NCOLS]              384
//  b2s   [8]                    8
//  leafs [64]                  64
//  part  [48][65]            3120   (padded pitch 65: avoid 32-way bank conflict)
//  probs [64][8]              512
#define SMEM_FLOATS (8192 + 6144 + 384 + 384 + 8 + 64 + 48*65 + 64*8)
#define SMEM_BYTES  (SMEM_FLOATS * 4)

__global__ __launch_bounds__(THREADS, 1)
void sdt_kernel(const float* __restrict__ x,
                const float* __restrict__ W1,
                const float* __restrict__ b1,
                const float* __restrict__ W2,
                const float* __restrict__ b2,
                const float* __restrict__ leaf,
                float* __restrict__ out)
{
    extern __shared__ float smem[];
    float* Xs    = smem;                    // 8192
    float* Bs    = Xs + BM * KDIM;          // 6144
    float* b1s   = Bs + KC * NCOLS;         // 384
    float* W2s   = b1s + NCOLS;             // 384
    float* b2s   = W2s + NCOLS;             // 8
    float* leafs = b2s + 8;                 // 64
    float* part  = leafs + 64;              // 48*65
    float* probs = part + 48 * 65;          // 64*8

    const int tid = threadIdx.x;
    const int tix = tid % 48;               // column group: 8 cols each
    const int tiy = tid / 48;               // row group: 8 rows each
    const int rowbase = blockIdx.x * BM;

    // ---- load X tile (coalesced float4, no transpose) ----
    {
        const float4* xg = (const float4*)x;
        float4* xs4 = (float4*)Xs;
        #pragma unroll
        for (int idx = tid; idx < BM * (KDIM / 4); idx += THREADS) {
            int row = idx >> 5;             // KDIM/4 = 32 float4 per row
            int d4  = idx & 31;
            xs4[row * 32 + d4] = xg[(size_t)(rowbase + row) * 32 + d4];
        }
    }

    // ---- load small tensors for the live 6 nodes ----
    {
        int node = tid >> 6, h = tid & 63;  // tid < 384 always
        int g = NODE_IDS[node] * 64 + h;
        b1s[tid] = b1[g];
        W2s[tid] = W2[g];
        if (tid < 6)  b2s[tid]   = b2[NODE_IDS[tid]];
        if (tid < 64) leafs[tid] = leaf[tid];
    }

    // ---- main GEMM: 8x8 register tile per thread ----
    float acc[8][8];
    #pragma unroll
    for (int s = 0; s < 8; s++)
        #pragma unroll
        for (int j = 0; j < 8; j++) acc[s][j] = 0.0f;

    const int a_row0 = tiy * 8;
    const int b_col0 = tix * 8;

    for (int kc = 0; kc < KDIM / KC; kc++) {
        __syncthreads();
        // stage W1 chunk [KC x NCOLS] into Bs (1536 float4, coalesced per node)
        #pragma unroll
        for (int idx = tid; idx < KC * NCOLS / 4; idx += THREADS) {
            int k  = idx / 96;              // 96 float4 per k-row
            int n4 = idx % 96;
            int n  = n4 * 4;
            int node = n >> 6, h = n & 63;
            const float4* src = (const float4*)(W1 + (size_t)NODE_IDS[node] * (KDIM * 64)
                                                + (size_t)(kc * KC + k) * 64 + h);
            ((float4*)Bs)[idx] = *src;
        }
        __syncthreads();

        #pragma unroll
        for (int k = 0; k < KC; k++) {
            float a[8];
            #pragma unroll
            for (int s = 0; s < 8; s++)
                a[s] = Xs[(a_row0 + s) * KDIM + kc * KC + k];
            float4 bv0 = *(const float4*)&Bs[k * NCOLS + b_col0];
            float4 bv1 = *(const float4*)&Bs[k * NCOLS + b_col0 + 4];
            float b[8] = {bv0.x, bv0.y, bv0.z, bv0.w, bv1.x, bv1.y, bv1.z, bv1.w};
            #pragma unroll
            for (int s = 0; s < 8; s++)
                #pragma unroll
                for (int j = 0; j < 8; j++)
                    acc[s][j] = fmaf(a[s], b[j], acc[s][j]);
        }
    }

    // ---- epilogue stage 1: per-thread partial  sum_j relu(h)*W2  (cols within one node) ----
    {
        #pragma unroll
        for (int s = 0; s < 8; s++) {
            float psum = 0.0f;
            #pragma unroll
            for (int j = 0; j < 8; j++) {
                float hv = acc[s][j] + b1s[b_col0 + j];
                hv = fmaxf(hv, 0.0f);
                psum = fmaf(hv, W2s[b_col0 + j], psum);
            }
            part[tix * 65 + a_row0 + s] = psum;
        }
    }
    __syncthreads();

    // ---- epilogue stage 2: reduce 8 partials -> sigmoid ----
    {
        int row = tid / 6, node = tid % 6;  // 384 = 64*6
        float sum = b2s[node];
        #pragma unroll
        for (int q = 0; q < 8; q++)
            sum += part[(node * 8 + q) * 65 + row];
        probs[row * 8 + node] = 1.0f / (1.0f + __expf(-sum));
    }
    __syncthreads();

    // ---- epilogue stage 3: 6-level leaf fold ----
    if (tid < 64) {
        int row = tid;
        float p[6];
        #pragma unroll
        for (int k = 0; k < 6; k++) p[k] = probs[row * 8 + k];

        float v[32];
        #pragma unroll
        for (int m = 0; m < 32; m++)
            v[m] = fmaf(p[0], leafs[2 * m + 1], (1.0f - p[0]) * leafs[2 * m]);
        #pragma unroll
        for (int k = 1; k < 6; k++) {
            int len = 32 >> k;
            #pragma unroll
            for (int m = 0; m < 32; m++) {
                if (m < len)
                    v[m] = fmaf(p[k], v[2 * m + 1], (1.0f - p[k]) * v[2 * m]);
            }
        }
        out[rowbase + row] = v[0];
    }
}

extern "C" void kernel_launch(void* const* d_in, const int* in_sizes, int n_in,
                              void* d_out, int out_size)
{
    const float* x    = (const float*)d_in[0];
    const float* W1   = (const float*)d_in[1];
    const float* b1   = (const float*)d_in[2];
    const float* W2   = (const float*)d_in[3];
    const float* b2   = (const float*)d_in[4];
    const float* leaf = (const float*)d_in[5];
    float* out = (float*)d_out;

    cudaFuncSetAttribute(sdt_kernel, cudaFuncAttributeMaxDynamicSharedMemorySize, SMEM_BYTES);

    int nblocks = 65536 / BM;   // 1024
    sdt_kernel<<<nblocks, THREADS, SMEM_BYTES>>>(x, W1, b1, W2, b2, leaf, out);
}

// round 3
// speedup vs baseline: 1.7762x; 1.7762x over previous
#include <cuda_runtime.h>
#include <cuda_bf16.h>
#include <cstdint>

// Soft decision tree forward via mma.sync bf16 (family-common HMMA path;
// tcgen05 is unavailable: harness PTX target is sm_103 without the 'a' suffix).
//
// Only chain nodes (2^k)-1, k=0..5 are used -> N = 6*64 = 384.
// GEMM: H[65536 x 384] = X[65536 x 128] @ W1cat[128 x 384] in fp32 via bf16
// 3-term split (xh*wh + xh*wl + xl*wh), fp32 accumulate in registers.
// Fused epilogue: relu -> dot W2 -> sigmoid -> 6-level leaf fold.

#define THREADS 384      // 12 warps: wm = wid&1 (M half), wn = wid>>1 (node 0..5)
#define M_CTA   128
#define KDIM    128
#define NTOT    384
#define NCTAS   512      // 65536 / 128
#define PITCH   20       // u32 pitch for 16 data u32 per row (bank-conflict-free)

// pre-converted W1 (live nodes only), row-major [n=384][k=128] bf16
__device__ __align__(16) __nv_bfloat16 g_Whi[NTOT * KDIM];
__device__ __align__(16) __nv_bfloat16 g_Wlo[NTOT * KDIM];

// ---- smem layout (u32/float units) ----
#define OFF_B1    0
#define OFF_W2    384
#define OFF_B2    768
#define OFF_LEAF  840
#define OFF_RS    912              // rowsum[6][132]
#define OFF_XH    1712
#define OFF_XL    (1712 + 2560)   // 4272
#define OFF_WH    (4272 + 2560)   // 6832
#define OFF_WL    (6832 + 7680)   // 14512
#define SMEM_U32  (14512 + 7680)  // 22192
#define SMEM_BYTES (SMEM_U32 * 4) // 88768

// ---------------- pre-kernel: W1 -> bf16 hi/lo ----------------
__global__ void convert_w1_kernel(const float* __restrict__ W1) {
    int idx = blockIdx.x * blockDim.x + threadIdx.x;
    if (idx >= NTOT * KDIM) return;
    int k = idx & 127;
    int n = idx >> 7;                 // 0..383
    int node = n >> 6, h = n & 63;
    int gnode = (1 << node) - 1;      // chain node ids 0,1,3,7,15,31
    float v = W1[(size_t)gnode * (KDIM * 64) + (size_t)k * 64 + h];
    __nv_bfloat16 hi = __float2bfloat16(v);
    __nv_bfloat16 lo = __float2bfloat16(v - __bfloat162float(hi));
    g_Whi[n * KDIM + k] = hi;
    g_Wlo[n * KDIM + k] = lo;
}

// ---------------- mma wrapper ----------------
__device__ __forceinline__ void mma_bf16(float* c, const uint32_t* a,
                                         uint32_t b0, uint32_t b1) {
    asm volatile(
        "mma.sync.aligned.m16n8k16.row.col.f32.bf16.bf16.f32 "
        "{%0,%1,%2,%3}, {%4,%5,%6,%7}, {%8,%9}, {%0,%1,%2,%3};"
        : "+f"(c[0]), "+f"(c[1]), "+f"(c[2]), "+f"(c[3])
        : "r"(a[0]), "r"(a[1]), "r"(a[2]), "r"(a[3]), "r"(b0), "r"(b1));
}

// ---------------- main kernel ----------------
__global__ __launch_bounds__(THREADS, 1)
void sdt_hmma_kernel(const float* __restrict__ x,
                     const float* __restrict__ b1,
                     const float* __restrict__ W2,
                     const float* __restrict__ b2,
                     const float* __restrict__ leaf,
                     float* __restrict__ out)
{
    extern __shared__ uint32_t smem[];
    float*    b1s   = (float*)(smem + OFF_B1);
    float*    W2s   = (float*)(smem + OFF_W2);
    float*    b2s   = (float*)(smem + OFF_B2);
    float*    leafs = (float*)(smem + OFF_LEAF);
    float*    rowsum= (float*)(smem + OFF_RS);
    uint32_t* XsH = smem + OFF_XH;
    uint32_t* XsL = smem + OFF_XL;
    uint32_t* WsH = smem + OFF_WH;
    uint32_t* WsL = smem + OFF_WL;

    const int tid  = threadIdx.x;
    const int lane = tid & 31;
    const int wid  = tid >> 5;
    const int wm   = wid & 1;        // M half (0/1)
    const int wn   = wid >> 1;       // node (0..5)
    const int g    = lane >> 2;      // group id 0..7
    const int t4   = lane & 3;
    const int rowbase = blockIdx.x * M_CTA;

    // small tensors for the 6 live nodes
    for (int i = tid; i < NTOT; i += THREADS) {
        int node = i >> 6, h = i & 63;
        int gl = ((1 << node) - 1) * 64 + h;
        b1s[i] = b1[gl];
        W2s[i] = W2[gl];
    }
    if (tid < 6)  b2s[tid]   = b2[(1 << tid) - 1];
    if (tid < 64) leafs[tid] = leaf[tid];

    float acc[4][8][4];
    #pragma unroll
    for (int mt = 0; mt < 4; mt++)
        #pragma unroll
        for (int nt = 0; nt < 8; nt++)
            #pragma unroll
            for (int j = 0; j < 4; j++) acc[mt][nt][j] = 0.0f;

    // ---- k-chunk loop: 4 chunks of k=32 ----
    for (int kc = 0; kc < 4; kc++) {
        __syncthreads();
        // stage W hi/lo chunk [384 n][32 k] bf16 -> packed u32 rows, pitch 20
        for (int idx = tid; idx < 1536; idx += THREADS) {
            int vec = idx & 3;            // 4 x int4 (16B) per row
            int n   = idx >> 2;           // 0..383
            int4 vh = *((const int4*)(g_Whi + n * KDIM + kc * 32) + vec);
            int4 vl = *((const int4*)(g_Wlo + n * KDIM + kc * 32) + vec);
            *(int4*)(WsH + n * PITCH + vec * 4) = vh;
            *(int4*)(WsL + n * PITCH + vec * 4) = vl;
        }
        // stage X chunk [128 rows][32 k] fp32 -> bf16 hi/lo packed
        for (int idx = tid; idx < 1024; idx += THREADS) {
            int c4  = idx & 7;            // 8 x float4 per row
            int row = idx >> 3;
            float4 v = *((const float4*)x + (size_t)(rowbase + row) * 32 + kc * 8 + c4);
            __nv_bfloat16 h0 = __float2bfloat16(v.x), h1 = __float2bfloat16(v.y);
            __nv_bfloat16 h2 = __float2bfloat16(v.z), h3 = __float2bfloat16(v.w);
            __nv_bfloat16 l0 = __float2bfloat16(v.x - __bfloat162float(h0));
            __nv_bfloat16 l1 = __float2bfloat16(v.y - __bfloat162float(h1));
            __nv_bfloat16 l2 = __float2bfloat16(v.z - __bfloat162float(h2));
            __nv_bfloat16 l3 = __float2bfloat16(v.w - __bfloat162float(h3));
            uint2 ph, pl;
            ph.x = ((uint32_t)__bfloat16_as_ushort(h1) << 16) | __bfloat16_as_ushort(h0);
            ph.y = ((uint32_t)__bfloat16_as_ushort(h3) << 16) | __bfloat16_as_ushort(h2);
            pl.x = ((uint32_t)__bfloat16_as_ushort(l1) << 16) | __bfloat16_as_ushort(l0);
            pl.y = ((uint32_t)__bfloat16_as_ushort(l3) << 16) | __bfloat16_as_ushort(l2);
            *(uint2*)(XsH + row * PITCH + c4 * 2) = ph;
            *(uint2*)(XsL + row * PITCH + c4 * 2) = pl;
        }
        __syncthreads();

        // ---- compute: 2 k-steps of 16 ----
        #pragma unroll
        for (int ks = 0; ks < 2; ks++) {
            const int kb = ks * 8;
            uint32_t A[4][4];
            // load A_hi frags
            #pragma unroll
            for (int mt = 0; mt < 4; mt++) {
                int r0 = (wm * 64 + mt * 16 + g) * PITCH + kb + t4;
                A[mt][0] = XsH[r0];
                A[mt][1] = XsH[r0 + 8 * PITCH];
                A[mt][2] = XsH[r0 + 4];
                A[mt][3] = XsH[r0 + 8 * PITCH + 4];
            }
            // pass 1: Ah * Bh
            #pragma unroll
            for (int nt = 0; nt < 8; nt++) {
                int bo = (wn * 64 + nt * 8 + g) * PITCH + kb + t4;
                uint32_t B0 = WsH[bo], B1 = WsH[bo + 4];
                #pragma unroll
                for (int mt = 0; mt < 4; mt++) mma_bf16(acc[mt][nt], A[mt], B0, B1);
            }
            // pass 2: Ah * Bl
            #pragma unroll
            for (int nt = 0; nt < 8; nt++) {
                int bo = (wn * 64 + nt * 8 + g) * PITCH + kb + t4;
                uint32_t B0 = WsL[bo], B1 = WsL[bo + 4];
                #pragma unroll
                for (int mt = 0; mt < 4; mt++) mma_bf16(acc[mt][nt], A[mt], B0, B1);
            }
            // load A_lo frags (overwrite)
            #pragma unroll
            for (int mt = 0; mt < 4; mt++) {
                int r0 = (wm * 64 + mt * 16 + g) * PITCH + kb + t4;
                A[mt][0] = XsL[r0];
                A[mt][1] = XsL[r0 + 8 * PITCH];
                A[mt][2] = XsL[r0 + 4];
                A[mt][3] = XsL[r0 + 8 * PITCH + 4];
            }
            // pass 3: Al * Bh
            #pragma unroll
            for (int nt = 0; nt < 8; nt++) {
                int bo = (wn * 64 + nt * 8 + g) * PITCH + kb + t4;
                uint32_t B0 = WsH[bo], B1 = WsH[bo + 4];
                #pragma unroll
                for (int mt = 0; mt < 4; mt++) mma_bf16(acc[mt][nt], A[mt], B0, B1);
            }
        }
    }

    // ---- fused epilogue ----
    // per-thread b1/W2 for this warp's 16 columns
    float b1v[16], W2v[16];
    #pragma unroll
    for (int nt = 0; nt < 8; nt++) {
        int col = wn * 64 + nt * 8 + t4 * 2;
        b1v[2 * nt]     = b1s[col];
        b1v[2 * nt + 1] = b1s[col + 1];
        W2v[2 * nt]     = W2s[col];
        W2v[2 * nt + 1] = W2s[col + 1];
    }
    __syncthreads();   // also guards rowsum region reuse

    #pragma unroll
    for (int mt = 0; mt < 4; mt++) {
        float s0 = 0.0f, s1 = 0.0f;   // rows g and g+8 of this m-tile
        #pragma unroll
        for (int nt = 0; nt < 8; nt++) {
            s0 = fmaf(fmaxf(acc[mt][nt][0] + b1v[2 * nt], 0.0f),     W2v[2 * nt], s0);
            s0 = fmaf(fmaxf(acc[mt][nt][1] + b1v[2 * nt + 1], 0.0f), W2v[2 * nt + 1], s0);
            s1 = fmaf(fmaxf(acc[mt][nt][2] + b1v[2 * nt], 0.0f),     W2v[2 * nt], s1);
            s1 = fmaf(fmaxf(acc[mt][nt][3] + b1v[2 * nt + 1], 0.0f), W2v[2 * nt + 1], s1);
        }
        // reduce across the 4 lanes of each quad (t4)
        s0 += __shfl_xor_sync(0xffffffffu, s0, 1);
        s0 += __shfl_xor_sync(0xffffffffu, s0, 2);
        s1 += __shfl_xor_sync(0xffffffffu, s1, 1);
        s1 += __shfl_xor_sync(0xffffffffu, s1, 2);
        if (t4 == 0) {
            int r = wm * 64 + mt * 16 + g;
            rowsum[wn * 132 + r]     = s0;
            rowsum[wn * 132 + r + 8] = s1;
        }
    }
    __syncthreads();

    if (tid < M_CTA) {
        float p[6];
        #pragma unroll
        for (int k = 0; k < 6; k++) {
            float z = rowsum[k * 132 + tid] + b2s[k];
            p[k] = 1.0f / (1.0f + __expf(-z));
        }
        float v[32];
        #pragma unroll
        for (int m = 0; m < 32; m++)
            v[m] = fmaf(p[0], leafs[2 * m + 1], (1.0f - p[0]) * leafs[2 * m]);
        #pragma unroll
        for (int k = 1; k < 6; k++) {
            int len = 32 >> k;
            #pragma unroll
            for (int m = 0; m < 32; m++)
                if (m < len)
                    v[m] = fmaf(p[k], v[2 * m + 1], (1.0f - p[k]) * v[2 * m]);
        }
        out[rowbase + tid] = v[0];
    }
}

// ---------------- launch ----------------
extern "C" void kernel_launch(void* const* d_in, const int* in_sizes, int n_in,
                              void* d_out, int out_size)
{
    const float* x    = (const float*)d_in[0];
    const float* W1   = (const float*)d_in[1];
    const float* b1   = (const float*)d_in[2];
    const float* W2   = (const float*)d_in[3];
    const float* b2   = (const float*)d_in[4];
    const float* leaf = (const float*)d_in[5];
    float* out = (float*)d_out;

    cudaFuncSetAttribute(sdt_hmma_kernel, cudaFuncAttributeMaxDynamicSharedMemorySize, SMEM_BYTES);

    convert_w1_kernel<<<(NTOT * KDIM + 255) / 256, 256>>>(W1);
    sdt_hmma_kernel<<<NCTAS, THREADS, SMEM_BYTES>>>(x, b1, W2, b2, leaf, out);
}

// round 4
// speedup vs baseline: 1.9485x; 1.0970x over previous
#include <cuda_runtime.h>
#include <cuda_bf16.h>
#include <cstdint>

// Soft decision tree forward via mma.sync bf16 (HMMA; tcgen05 not available:
// harness PTX target is family-common sm_103).
// Chain nodes (2^k)-1, k=0..5 -> N = 6*64 = 384.
// GEMM H = X[65536x128] @ W1cat[128x384] via bf16 3-term split, fp32 accum.
// R4: ldmatrix fragment loads + cp.async double-buffered W + register-prefetched X.

#define THREADS 384      // 12 warps: wm = wid&1 (M half), wn = wid>>1 (node)
#define M_CTA   128
#define KDIM    128
#define NTOT    384
#define NCTAS   512

// pre-converted W1 (live nodes only), row-major [n=384][k=128] bf16
__device__ __align__(16) __nv_bfloat16 g_Whi[NTOT * KDIM];
__device__ __align__(16) __nv_bfloat16 g_Wlo[NTOT * KDIM];

// ---- smem layout (bytes) ----
// tables: b1[384]f32, W2[384]f32, b2[8], leaf[64], rowsum[6][132]
#define OFF_B1    0
#define OFF_W2    1536
#define OFF_B2    3072
#define OFF_LEAF  3104
#define OFF_RS    3360                  // 6*132*4 = 3168
#define OFF_X     6656                  // X: 2 terms x 128 rows x 80B = 20480
#define X_TERM    10240
#define OFF_W     27136                 // W: 2 buf x 2 terms x 384 x 80B
#define W_REGION  30720
#define SMEM_BYTES (27136 + 4 * 30720) // 150016

// ---------------- pre-kernel: W1 -> bf16 hi/lo ----------------
__global__ void convert_w1_kernel(const float* __restrict__ W1) {
    int idx = blockIdx.x * blockDim.x + threadIdx.x;
    if (idx >= NTOT * KDIM) return;
    int k = idx & 127;
    int n = idx >> 7;
    int node = n >> 6, h = n & 63;
    int gnode = (1 << node) - 1;
    float v = W1[(size_t)gnode * (KDIM * 64) + (size_t)k * 64 + h];
    __nv_bfloat16 hi = __float2bfloat16(v);
    __nv_bfloat16 lo = __float2bfloat16(v - __bfloat162float(hi));
    g_Whi[n * KDIM + k] = hi;
    g_Wlo[n * KDIM + k] = lo;
}

// ---------------- asm helpers ----------------
__device__ __forceinline__ uint32_t smem_u32_of(const void* p) {
    uint32_t a;
    asm("{ .reg .u64 t; cvta.to.shared.u64 t, %1; cvt.u32.u64 %0, t; }"
        : "=r"(a) : "l"(p));
    return a;
}
__device__ __forceinline__ void cp_async16(uint32_t dst, const void* src) {
    asm volatile("cp.async.cg.shared.global [%0], [%1], 16;" :: "r"(dst), "l"(src));
}
__device__ __forceinline__ void ldsm_x4(uint32_t& r0, uint32_t& r1,
                                        uint32_t& r2, uint32_t& r3, uint32_t addr) {
    asm volatile("ldmatrix.sync.aligned.m8n8.x4.shared.b16 {%0,%1,%2,%3}, [%4];"
                 : "=r"(r0), "=r"(r1), "=r"(r2), "=r"(r3) : "r"(addr));
}
__device__ __forceinline__ void mma_bf16(float* c, const uint32_t* a,
                                         uint32_t b0, uint32_t b1) {
    asm volatile(
        "mma.sync.aligned.m16n8k16.row.col.f32.bf16.bf16.f32 "
        "{%0,%1,%2,%3}, {%4,%5,%6,%7}, {%8,%9}, {%0,%1,%2,%3};"
        : "+f"(c[0]), "+f"(c[1]), "+f"(c[2]), "+f"(c[3])
        : "r"(a[0]), "r"(a[1]), "r"(a[2]), "r"(a[3]), "r"(b0), "r"(b1));
}

// ---------------- main kernel ----------------
__global__ __launch_bounds__(THREADS, 1)
void sdt_hmma_kernel(const float* __restrict__ x,
                     const float* __restrict__ b1,
                     const float* __restrict__ W2,
                     const float* __restrict__ b2,
                     const float* __restrict__ leaf,
                     float* __restrict__ out)
{
    extern __shared__ char smem[];
    const uint32_t sbase = smem_u32_of(smem);
    float* b1s    = (float*)(smem + OFF_B1);
    float* W2s    = (float*)(smem + OFF_W2);
    float* b2s    = (float*)(smem + OFF_B2);
    float* leafs  = (float*)(smem + OFF_LEAF);
    float* rowsum = (float*)(smem + OFF_RS);

    const int tid  = threadIdx.x;
    const int lane = tid & 31;
    const int wid  = tid >> 5;
    const int wm   = wid & 1;
    const int wn   = wid >> 1;
    const int g    = lane >> 2;
    const int t4   = lane & 3;
    const int rowbase = blockIdx.x * M_CTA;

    // small tensors
    for (int i = tid; i < NTOT; i += THREADS) {
        int node = i >> 6, h = i & 63;
        int gl = ((1 << node) - 1) * 64 + h;
        b1s[i] = b1[gl];
        W2s[i] = W2[gl];
    }
    if (tid < 6)  b2s[tid]   = b2[(1 << tid) - 1];
    if (tid < 64) leafs[tid] = leaf[tid];

    float acc[4][8][4];
    #pragma unroll
    for (int mt = 0; mt < 4; mt++)
        #pragma unroll
        for (int nt = 0; nt < 8; nt++)
            #pragma unroll
            for (int j = 0; j < 4; j++) acc[mt][nt][j] = 0.0f;

    // ---- per-thread staging indices ----
    // X: chunk = 128 rows x 8 float4 (32 k); thread handles tid, tid+384, tid+768
    const float4* xg = (const float4*)x;
    const int xi0 = tid, xi1 = tid + 384, xi2 = tid + 768;   // xi2 valid iff tid<256

    // W cp.async: per term 1536 16B ops (row=idx>>2, v=idx&3), thread stride 384
    // ldmatrix lane offsets
    const int a_row  = wm * 64 + (lane & 15);
    const uint32_t a_loff = (uint32_t)a_row * 80u + (uint32_t)((lane >> 4) << 4);
    const int b_row  = (lane & 7) + (((lane >> 4) & 1) << 3);
    const uint32_t b_loff = (uint32_t)(wn * 64 + b_row) * 80u
                          + (uint32_t)(((lane >> 3) & 1) << 4);

    // ---- prologue: prefetch chunk 0 ----
    {   // W chunk 0 -> buf 0
        const uint32_t wdstH = sbase + OFF_W;               // buf0 term0
        const uint32_t wdstL = sbase + OFF_W + W_REGION;    // buf0 term1
        #pragma unroll
        for (int it = 0; it < 4; it++) {
            int idx = tid + it * 384;
            int row = idx >> 2, v = idx & 3;
            cp_async16(wdstH + row * 80 + v * 16, g_Whi + row * KDIM + v * 8);
            cp_async16(wdstL + row * 80 + v * 16, g_Wlo + row * KDIM + v * 8);
        }
        asm volatile("cp.async.commit_group;" ::: "memory");
    }
    float4 cur0 = xg[(size_t)(rowbase + (xi0 >> 3)) * 32 + (xi0 & 7)];
    float4 cur1 = xg[(size_t)(rowbase + (xi1 >> 3)) * 32 + (xi1 & 7)];
    float4 cur2 = (tid < 256) ? xg[(size_t)(rowbase + (xi2 >> 3)) * 32 + (xi2 & 7)]
                              : make_float4(0.f, 0.f, 0.f, 0.f);

    for (int kc = 0; kc < 4; kc++) {
        const int bb = kc & 1;

        // convert & store X chunk kc (hi/lo) into the single X stage
        {
            uint32_t* XsH = (uint32_t*)(smem + OFF_X);
            uint32_t* XsL = (uint32_t*)(smem + OFF_X + X_TERM);
            float4 v[3] = {cur0, cur1, cur2};
            int xi[3] = {xi0, xi1, xi2};
            #pragma unroll
            for (int q = 0; q < 3; q++) {
                if (q == 2 && tid >= 256) break;
                int row = xi[q] >> 3, c4 = xi[q] & 7;
                __nv_bfloat16 h0 = __float2bfloat16(v[q].x), h1 = __float2bfloat16(v[q].y);
                __nv_bfloat16 h2 = __float2bfloat16(v[q].z), h3 = __float2bfloat16(v[q].w);
                __nv_bfloat16 l0 = __float2bfloat16(v[q].x - __bfloat162float(h0));
                __nv_bfloat16 l1 = __float2bfloat16(v[q].y - __bfloat162float(h1));
                __nv_bfloat16 l2 = __float2bfloat16(v[q].z - __bfloat162float(h2));
                __nv_bfloat16 l3 = __float2bfloat16(v[q].w - __bfloat162float(h3));
                uint2 ph, pl;
                ph.x = ((uint32_t)__bfloat16_as_ushort(h1) << 16) | __bfloat16_as_ushort(h0);
                ph.y = ((uint32_t)__bfloat16_as_ushort(h3) << 16) | __bfloat16_as_ushort(h2);
                pl.x = ((uint32_t)__bfloat16_as_ushort(l1) << 16) | __bfloat16_as_ushort(l0);
                pl.y = ((uint32_t)__bfloat16_as_ushort(l3) << 16) | __bfloat16_as_ushort(l2);
                *(uint2*)(XsH + row * 20 + c4 * 2) = ph;
                *(uint2*)(XsL + row * 20 + c4 * 2) = pl;
            }
        }

        // prefetch chunk kc+1: W via cp.async into other buf, X raw into regs
        if (kc < 3) {
            const uint32_t wdstH = sbase + OFF_W + (uint32_t)(1 - bb) * 2u * W_REGION;
            const uint32_t wdstL = wdstH + W_REGION;
            const int ko = (kc + 1) * 32;
            #pragma unroll
            for (int it = 0; it < 4; it++) {
                int idx = tid + it * 384;
                int row = idx >> 2, v = idx & 3;
                cp_async16(wdstH + row * 80 + v * 16, g_Whi + row * KDIM + ko + v * 8);
                cp_async16(wdstL + row * 80 + v * 16, g_Wlo + row * KDIM + ko + v * 8);
            }
            asm volatile("cp.async.commit_group;" ::: "memory");
            cur0 = xg[(size_t)(rowbase + (xi0 >> 3)) * 32 + (kc + 1) * 8 + (xi0 & 7)];
            cur1 = xg[(size_t)(rowbase + (xi1 >> 3)) * 32 + (kc + 1) * 8 + (xi1 & 7)];
            if (tid < 256)
                cur2 = xg[(size_t)(rowbase + (xi2 >> 3)) * 32 + (kc + 1) * 8 + (xi2 & 7)];
            asm volatile("cp.async.wait_group 1;" ::: "memory");
        } else {
            asm volatile("cp.async.wait_group 0;" ::: "memory");
        }
        __syncthreads();

        // ---- compute chunk kc from smem (W buf bb) ----
        const uint32_t xhb = sbase + OFF_X;
        const uint32_t xlb = sbase + OFF_X + X_TERM;
        const uint32_t whb = sbase + OFF_W + (uint32_t)bb * 2u * W_REGION;
        const uint32_t wlb = whb + W_REGION;

        #pragma unroll
        for (int ks = 0; ks < 2; ks++) {
            const uint32_t kso = (uint32_t)(ks * 32);
            uint32_t A[4][4];
            #pragma unroll
            for (int mt = 0; mt < 4; mt++)
                ldsm_x4(A[mt][0], A[mt][1], A[mt][2], A[mt][3],
                        xhb + a_loff + (uint32_t)(mt * 1280) + kso);
            // pass 1: Ah*Bh ; pass 2: Ah*Bl
            #pragma unroll
            for (int t = 0; t < 2; t++) {
                const uint32_t wb = t ? wlb : whb;
                #pragma unroll
                for (int p = 0; p < 4; p++) {
                    uint32_t b0, b1v_, b2v_, b3;
                    ldsm_x4(b0, b1v_, b2v_, b3, wb + b_loff + (uint32_t)(p * 1280) + kso);
                    #pragma unroll
                    for (int mt = 0; mt < 4; mt++) {
                        mma_bf16(acc[mt][2 * p],     A[mt], b0,    b1v_);
                        mma_bf16(acc[mt][2 * p + 1], A[mt], b2v_,  b3);
                    }
                }
            }
            // pass 3: Al*Bh
            #pragma unroll
            for (int mt = 0; mt < 4; mt++)
                ldsm_x4(A[mt][0], A[mt][1], A[mt][2], A[mt][3],
                        xlb + a_loff + (uint32_t)(mt * 1280) + kso);
            #pragma unroll
            for (int p = 0; p < 4; p++) {
                uint32_t b0, b1v_, b2v_, b3;
                ldsm_x4(b0, b1v_, b2v_, b3, whb + b_loff + (uint32_t)(p * 1280) + kso);
                #pragma unroll
                for (int mt = 0; mt < 4; mt++) {
                    mma_bf16(acc[mt][2 * p],     A[mt], b0,   b1v_);
                    mma_bf16(acc[mt][2 * p + 1], A[mt], b2v_, b3);
                }
            }
        }
        __syncthreads();
    }

    // ---- fused epilogue ----
    float b1v[16], W2v[16];
    #pragma unroll
    for (int nt = 0; nt < 8; nt++) {
        int col = wn * 64 + nt * 8 + t4 * 2;
        b1v[2 * nt]     = b1s[col];
        b1v[2 * nt + 1] = b1s[col + 1];
        W2v[2 * nt]     = W2s[col];
        W2v[2 * nt + 1] = W2s[col + 1];
    }

    #pragma unroll
    for (int mt = 0; mt < 4; mt++) {
        float s0 = 0.0f, s1 = 0.0f;
        #pragma unroll
        for (int nt = 0; nt < 8; nt++) {
            s0 = fmaf(fmaxf(acc[mt][nt][0] + b1v[2 * nt], 0.0f),     W2v[2 * nt], s0);
            s0 = fmaf(fmaxf(acc[mt][nt][1] + b1v[2 * nt + 1], 0.0f), W2v[2 * nt + 1], s0);
            s1 = fmaf(fmaxf(acc[mt][nt][2] + b1v[2 * nt], 0.0f),     W2v[2 * nt], s1);
            s1 = fmaf(fmaxf(acc[mt][nt][3] + b1v[2 * nt + 1], 0.0f), W2v[2 * nt + 1], s1);
        }
        s0 += __shfl_xor_sync(0xffffffffu, s0, 1);
        s0 += __shfl_xor_sync(0xffffffffu, s0, 2);
        s1 += __shfl_xor_sync(0xffffffffu, s1, 1);
        s1 += __shfl_xor_sync(0xffffffffu, s1, 2);
        if (t4 == 0) {
            int r = wm * 64 + mt * 16 + g;
            rowsum[wn * 132 + r]     = s0;
            rowsum[wn * 132 + r + 8] = s1;
        }
    }
    __syncthreads();

    if (tid < M_CTA) {
        float p[6];
        #pragma unroll
        for (int k = 0; k < 6; k++) {
            float z = rowsum[k * 132 + tid] + b2s[k];
            p[k] = 1.0f / (1.0f + __expf(-z));
        }
        float v[32];
        #pragma unroll
        for (int m = 0; m < 32; m++)
            v[m] = fmaf(p[0], leafs[2 * m + 1], (1.0f - p[0]) * leafs[2 * m]);
        #pragma unroll
        for (int k = 1; k < 6; k++) {
            int len = 32 >> k;
            #pragma unroll
            for (int m = 0; m < 32; m++)
                if (m < len)
                    v[m] = fmaf(p[k], v[2 * m + 1], (1.0f - p[k]) * v[2 * m]);
        }
        out[rowbase + tid] = v[0];
    }
}

// ---------------- launch ----------------
extern "C" void kernel_launch(void* const* d_in, const int* in_sizes, int n_in,
                              void* d_out, int out_size)
{
    const float* x    = (const float*)d_in[0];
    const float* W1   = (const float*)d_in[1];
    const float* b1   = (const float*)d_in[2];
    const float* W2   = (const float*)d_in[3];
    const float* b2   = (const float*)d_in[4];
    const float* leaf = (const float*)d_in[5];
    float* out = (float*)d_out;

    cudaFuncSetAttribute(sdt_hmma_kernel, cudaFuncAttributeMaxDynamicSharedMemorySize, SMEM_BYTES);

    convert_w1_kernel<<<(NTOT * KDIM + 255) / 256, 256>>>(W1);
    sdt_hmma_kernel<<<NCTAS, THREADS, SMEM_BYTES>>>(x, b1, W2, b2, leaf, out);
}

// round 6
// speedup vs baseline: 2.1586x; 1.1078x over previous
#include <cuda_runtime.h>
#include <cuda_bf16.h>
#include <cstdint>

// Soft decision tree forward via mma.sync TF32 single-pass (sm_103 family-common;
// tcgen05 unavailable in this toolchain path).
// Chain nodes (2^k)-1, k=0..5 -> N = 6*64 = 384.
// GEMM H = X[65536x128] @ W1cat[128x384], tf32 x tf32 -> fp32 accumulate.
// Fused epilogue: relu -> dot W2 -> sigmoid -> 6-level leaf fold.
// R5: single tf32 pass (-33% tensor instrs), paired-interleave smem layout
// (LDS.64 frag loads), double-buffered X+W, ONE __syncthreads per k-chunk.

#define THREADS 384      // 12 warps: wm = wid&1 (M half), wn = wid>>1 (node)
#define M_CTA   128
#define KDIM    128
#define NTOT    384
#define NCTAS   512
#define PITCH_F 40       // floats per row (160B): conflict-free LDS.64

// W1 (live nodes), tf32-rounded fp32, k interleaved within 8-blocks:
// slot(kk) = (kk&3)*2 + (kk>>2)  ->  slots (2*t4, 2*t4+1) hold k = t4, t4+4
__device__ __align__(16) float g_Wtf[NTOT * KDIM];

// ---- smem layout (bytes) ----
#define OFF_B1    0
#define OFF_W2    1536
#define OFF_B2    3072
#define OFF_LEAF  3104
#define OFF_RS    3360                 // rowsum 6*132*4 = 3168
#define OFF_X0    6656                 // 128 rows * 160B = 20480
#define OFF_X1    27136
#define OFF_W0    47616                // 384 rows * 160B = 61440
#define OFF_W1    109056
#define SMEM_BYTES 170496

// ---------------- helpers ----------------
__device__ __forceinline__ float to_tf32(float v) {
    uint32_t t;
    asm("cvt.rna.tf32.f32 %0, %1;" : "=r"(t) : "f"(v));
    return __uint_as_float(t);
}
__device__ __forceinline__ uint32_t smem_u32_of(const void* p) {
    uint32_t a;
    asm("{ .reg .u64 t; cvta.to.shared.u64 t, %1; cvt.u32.u64 %0, t; }"
        : "=r"(a) : "l"(p));
    return a;
}
__device__ __forceinline__ void cp_async16(uint32_t dst, const void* src) {
    asm volatile("cp.async.cg.shared.global [%0], [%1], 16;" :: "r"(dst), "l"(src));
}
__device__ __forceinline__ void lds64(uint32_t& a, uint32_t& b, uint32_t addr) {
    asm volatile("ld.shared.v2.u32 {%0,%1}, [%2];" : "=r"(a), "=r"(b) : "r"(addr));
}
__device__ __forceinline__ void mma_tf32(float* c, const uint32_t* a,
                                         uint32_t b0, uint32_t b1) {
    asm volatile(
        "mma.sync.aligned.m16n8k8.row.col.f32.tf32.tf32.f32 "
        "{%0,%1,%2,%3}, {%4,%5,%6,%7}, {%8,%9}, {%0,%1,%2,%3};"
        : "+f"(c[0]), "+f"(c[1]), "+f"(c[2]), "+f"(c[3])
        : "r"(a[0]), "r"(a[1]), "r"(a[2]), "r"(a[3]), "r"(b0), "r"(b1));
}

// ---------------- pre-kernel: W1 -> tf32, interleaved k layout ----------------
__global__ void convert_w1_kernel(const float* __restrict__ W1) {
    int idx = blockIdx.x * blockDim.x + threadIdx.x;
    if (idx >= NTOT * KDIM) return;
    int k = idx & 127;
    int n = idx >> 7;
    int node = n >> 6, h = n & 63;
    int gnode = (1 << node) - 1;            // 0,1,3,7,15,31
    float v = W1[(size_t)gnode * (KDIM * 64) + (size_t)k * 64 + h];
    int kk = k & 7, blk = k >> 3;
    int slot = (kk & 3) * 2 + (kk >> 2);
    g_Wtf[n * KDIM + blk * 8 + slot] = to_tf32(v);
}

// ---------------- main kernel ----------------
__global__ __launch_bounds__(THREADS, 1)
void sdt_tf32_kernel(const float* __restrict__ x,
                     const float* __restrict__ b1,
                     const float* __restrict__ W2,
                     const float* __restrict__ b2,
                     const float* __restrict__ leaf,
                     float* __restrict__ out)
{
    extern __shared__ char smem[];
    const uint32_t sbase = smem_u32_of(smem);
    float* b1s    = (float*)(smem + OFF_B1);
    float* W2s    = (float*)(smem + OFF_W2);
    float* b2s    = (float*)(smem + OFF_B2);
    float* leafs  = (float*)(smem + OFF_LEAF);
    float* rowsum = (float*)(smem + OFF_RS);

    const int tid  = threadIdx.x;
    const int lane = tid & 31;
    const int wid  = tid >> 5;
    const int wm   = wid & 1;
    const int wn   = wid >> 1;
    const int g    = lane >> 2;
    const int t4   = lane & 3;
    const int rowbase = blockIdx.x * M_CTA;

    // small tensors for the 6 live nodes
    for (int i = tid; i < NTOT; i += THREADS) {
        int node = i >> 6, h = i & 63;
        int gl = ((1 << node) - 1) * 64 + h;
        b1s[i] = b1[gl];
        W2s[i] = W2[gl];
    }
    if (tid < 6)  b2s[tid]   = b2[(1 << tid) - 1];
    if (tid < 64) leafs[tid] = leaf[tid];

    float acc[4][8][4];
    #pragma unroll
    for (int mt = 0; mt < 4; mt++)
        #pragma unroll
        for (int nt = 0; nt < 8; nt++)
            #pragma unroll
            for (int j = 0; j < 4; j++) acc[mt][nt][j] = 0.0f;

    // X indices: chunk = 128 rows x 8 float4; thread covers tid, tid+384, tid+768
    const float4* xg = (const float4*)x;
    const int xr0 = tid >> 3,        xc0 = tid & 7;
    const int xr1 = (tid + 384) >> 3, xc1 = (tid + 384) & 7;
    const int xr2 = (tid + 768) >> 3, xc2 = (tid + 768) & 7;   // valid iff tid<256

    // store one float4 (k = c4*4..c4*4+3 of chunk) into interleaved X layout
    auto storeX = [&](uint32_t xoff, int row, int c4, float4 v) {
        float* dst = (float*)(smem + xoff) + row * PITCH_F + (c4 >> 1) * 8;
        int base = (c4 & 1) * 4;     // kk = base + j
        float vv[4] = {v.x, v.y, v.z, v.w};
        #pragma unroll
        for (int j = 0; j < 4; j++) {
            int kk = base + j;
            dst[(kk & 3) * 2 + (kk >> 2)] = to_tf32(vv[j]);
        }
    };

    // W cp.async for chunk kc into wbuf (8 x 16B per thread)
    auto stageW = [&](uint32_t woff, int kc) {
        #pragma unroll
        for (int it = 0; it < 8; it++) {
            int idx = tid + it * 384;
            int row = idx >> 3, v = idx & 7;
            cp_async16(sbase + woff + row * 160 + v * 16,
                       g_Wtf + row * KDIM + kc * 32 + v * 4);
        }
        asm volatile("cp.async.commit_group;" ::: "memory");
    };

    // ---- prologue ----
    stageW(OFF_W0, 0);
    float4 cur0 = xg[(size_t)(rowbase + xr0) * 32 + xc0];
    float4 cur1 = xg[(size_t)(rowbase + xr1) * 32 + xc1];
    float4 cur2 = (tid < 256) ? xg[(size_t)(rowbase + xr2) * 32 + xc2]
                              : make_float4(0.f, 0.f, 0.f, 0.f);
    storeX(OFF_X0, xr0, xc0, cur0);
    storeX(OFF_X0, xr1, xc1, cur1);
    if (tid < 256) storeX(OFF_X0, xr2, xc2, cur2);
    cur0 = xg[(size_t)(rowbase + xr0) * 32 + 8 + xc0];
    cur1 = xg[(size_t)(rowbase + xr1) * 32 + 8 + xc1];
    if (tid < 256) cur2 = xg[(size_t)(rowbase + xr2) * 32 + 8 + xc2];

    const uint32_t a_base = sbase + (uint32_t)((wm * 64 + g) * 160 + t4 * 8);
    const uint32_t b_base = sbase + (uint32_t)((wn * 64 + g) * 160 + t4 * 8);

    for (int kc = 0; kc < 4; kc++) {
        const int bb = kc & 1;
        asm volatile("cp.async.wait_group 0;" ::: "memory");
        __syncthreads();
        // prefetch next chunk into the other buffers (hazard-free: sync above)
        if (kc < 3) {
            stageW(bb ? OFF_W0 : OFF_W1, kc + 1);
            uint32_t xo = bb ? OFF_X0 : OFF_X1;
            storeX(xo, xr0, xc0, cur0);
            storeX(xo, xr1, xc1, cur1);
            if (tid < 256) storeX(xo, xr2, xc2, cur2);
            if (kc < 2) {
                cur0 = xg[(size_t)(rowbase + xr0) * 32 + (kc + 2) * 8 + xc0];
                cur1 = xg[(size_t)(rowbase + xr1) * 32 + (kc + 2) * 8 + xc1];
                if (tid < 256)
                    cur2 = xg[(size_t)(rowbase + xr2) * 32 + (kc + 2) * 8 + xc2];
            }
        }

        // ---- compute chunk kc: 4 k-steps of 8 ----
        const uint32_t xb = a_base + (uint32_t)(bb ? OFF_X1 : OFF_X0);
        const uint32_t wb = b_base + (uint32_t)(bb ? OFF_W1 : OFF_W0);
        #pragma unroll
        for (int ks = 0; ks < 4; ks++) {
            const uint32_t kso = (uint32_t)(ks * 32);
            uint32_t A[4][4];
            #pragma unroll
            for (int mt = 0; mt < 4; mt++) {
                uint32_t r = xb + (uint32_t)(mt * 16 * 160) + kso;
                lds64(A[mt][0], A[mt][2], r);              // row g:   (t4, t4+4)
                lds64(A[mt][1], A[mt][3], r + 8 * 160);    // row g+8
            }
            #pragma unroll
            for (int nt = 0; nt < 8; nt++) {
                uint32_t b0, b1v_;
                lds64(b0, b1v_, wb + (uint32_t)(nt * 8 * 160) + kso);
                #pragma unroll
                for (int mt = 0; mt < 4; mt++)
                    mma_tf32(acc[mt][nt], A[mt], b0, b1v_);
            }
        }
    }

    // ---- fused epilogue ----
    float b1v[16], W2v[16];
    #pragma unroll
    for (int nt = 0; nt < 8; nt++) {
        int col = wn * 64 + nt * 8 + t4 * 2;
        b1v[2 * nt]     = b1s[col];
        b1v[2 * nt + 1] = b1s[col + 1];
        W2v[2 * nt]     = W2s[col];
        W2v[2 * nt + 1] = W2s[col + 1];
    }
    __syncthreads();

    #pragma unroll
    for (int mt = 0; mt < 4; mt++) {
        float s0 = 0.0f, s1 = 0.0f;
        #pragma unroll
        for (int nt = 0; nt < 8; nt++) {
            s0 = fmaf(fmaxf(acc[mt][nt][0] + b1v[2 * nt], 0.0f),     W2v[2 * nt], s0);
            s0 = fmaf(fmaxf(acc[mt][nt][1] + b1v[2 * nt + 1], 0.0f), W2v[2 * nt + 1], s0);
            s1 = fmaf(fmaxf(acc[mt][nt][2] + b1v[2 * nt], 0.0f),     W2v[2 * nt], s1);
            s1 = fmaf(fmaxf(acc[mt][nt][3] + b1v[2 * nt + 1], 0.0f), W2v[2 * nt + 1], s1);
        }
        s0 += __shfl_xor_sync(0xffffffffu, s0, 1);
        s0 += __shfl_xor_sync(0xffffffffu, s0, 2);
        s1 += __shfl_xor_sync(0xffffffffu, s1, 1);
        s1 += __shfl_xor_sync(0xffffffffu, s1, 2);
        if (t4 == 0) {
            int r = wm * 64 + mt * 16 + g;
            rowsum[wn * 132 + r]     = s0;
            rowsum[wn * 132 + r + 8] = s1;
        }
    }
    __syncthreads();

    if (tid < M_CTA) {
        float p[6];
        #pragma unroll
        for (int k = 0; k < 6; k++) {
            float z = rowsum[k * 132 + tid] + b2s[k];
            p[k] = 1.0f / (1.0f + __expf(-z));
        }
        float v[32];
        #pragma unroll
        for (int m = 0; m < 32; m++)
            v[m] = fmaf(p[0], leafs[2 * m + 1], (1.0f - p[0]) * leafs[2 * m]);
        #pragma unroll
        for (int k = 1; k < 6; k++) {
            int len = 32 >> k;
            #pragma unroll
            for (int m = 0; m < 32; m++)
                if (m < len)
                    v[m] = fmaf(p[k], v[2 * m + 1], (1.0f - p[k]) * v[2 * m]);
        }
        out[rowbase + tid] = v[0];
    }
}

// ---------------- launch ----------------
extern "C" void kernel_launch(void* const* d_in, const int* in_sizes, int n_in,
                              void* d_out, int out_size)
{
    const float* x    = (const float*)d_in[0];
    const float* W1   = (const float*)d_in[1];
    const float* b1   = (const float*)d_in[2];
    const float* W2   = (const float*)d_in[3];
    const float* b2   = (const float*)d_in[4];
    const float* leaf = (const float*)d_in[5];
    float* out = (float*)d_out;

    cudaFuncSetAttribute(sdt_tf32_kernel, cudaFuncAttributeMaxDynamicSharedMemorySize, SMEM_BYTES);

    convert_w1_kernel<<<(NTOT * KDIM + 255) / 256, 256>>>(W1);
    sdt_tf32_kernel<<<NCTAS, THREADS, SMEM_BYTES>>>(x, b1, W2, b2, leaf, out);
}

// round 7
// speedup vs baseline: 4.4041x; 2.0402x over previous
#include <cuda_runtime.h>
#include <cuda_fp16.h>
#include <cstdint>

// Soft decision tree forward via mma.sync fp16 single-pass (family-common sm_103;
// tcgen05 unavailable in this toolchain path).
// Chain nodes (2^k)-1, k=0..5 -> N = 6*64 = 384.
// GEMM H = X[65536x128] @ W1cat[128x384], fp16 x fp16 -> fp32 accumulate.
// Fused epilogue: relu -> dot W2 -> sigmoid -> 6-level leaf fold.
// R7: m16n8k16 fp16 (half the MMA instrs + half the frag LDS of tf32-k8),
// X staged once for all k, W double-buffered cp.async, 2 syncs total.

#define THREADS 384      // 12 warps: wm = wid&1 (M half), wn = wid>>1 (node)
#define M_CTA   128
#define KDIM    128
#define NTOT    384
#define NCTAS   512
#define XPITCH  288      // bytes/row: 256 data + 32 pad (72 words = 8 mod 32)
#define WPITCH  160      // bytes/row: 128 data + 32 pad (40 words = 8 mod 32)

// W1 (live nodes) fp16, [n=384][k=128], k permuted within 16-blocks so that
// pairs (2t4,2t4+1) and (2t4+8,2t4+9) are adjacent -> B frags = one LDS.64.
__device__ __align__(16) __half g_Wh[NTOT * KDIM];

// ---- smem layout (bytes) ----
#define OFF_B1    0
#define OFF_W2    1536
#define OFF_B2    3072
#define OFF_LEAF  3104
#define OFF_RS    3360                 // rowsum 6*132*4 = 3168 -> end 6528
#define OFF_X     6656                 // 128 rows * 288B = 36864
#define OFF_W0    43520                // 384 rows * 160B = 61440
#define OFF_W1    104960
#define SMEM_BYTES 166400

// ---------------- helpers ----------------
__device__ __forceinline__ uint32_t smem_u32_of(const void* p) {
    uint32_t a;
    asm("{ .reg .u64 t; cvta.to.shared.u64 t, %1; cvt.u32.u64 %0, t; }"
        : "=r"(a) : "l"(p));
    return a;
}
__device__ __forceinline__ void cp_async16(uint32_t dst, const void* src) {
    asm volatile("cp.async.cg.shared.global [%0], [%1], 16;" :: "r"(dst), "l"(src));
}
__device__ __forceinline__ void lds64(uint32_t& a, uint32_t& b, uint32_t addr) {
    asm volatile("ld.shared.v2.u32 {%0,%1}, [%2];" : "=r"(a), "=r"(b) : "r"(addr));
}
__device__ __forceinline__ void sts32(uint32_t addr, uint32_t v) {
    asm volatile("st.shared.u32 [%0], %1;" :: "r"(addr), "r"(v));
}
__device__ __forceinline__ void mma_fp16(float* c, const uint32_t* a,
                                         uint32_t b0, uint32_t b1) {
    asm volatile(
        "mma.sync.aligned.m16n8k16.row.col.f32.f16.f16.f32 "
        "{%0,%1,%2,%3}, {%4,%5,%6,%7}, {%8,%9}, {%0,%1,%2,%3};"
        : "+f"(c[0]), "+f"(c[1]), "+f"(c[2]), "+f"(c[3])
        : "r"(a[0]), "r"(a[1]), "r"(a[2]), "r"(a[3]), "r"(b0), "r"(b1));
}

// ---------------- pre-kernel: W1 -> fp16, permuted k ----------------
__global__ void convert_w1_kernel(const float* __restrict__ W1) {
    int idx = blockIdx.x * blockDim.x + threadIdx.x;
    if (idx >= NTOT * KDIM) return;
    int k = idx & 127;
    int n = idx >> 7;
    int node = n >> 6, h = n & 63;
    int gnode = (1 << node) - 1;            // 0,1,3,7,15,31
    float v = W1[(size_t)gnode * (KDIM * 64) + (size_t)k * 64 + h];
    int blk = k >> 4, kk = k & 15, q = kk >> 1;
    int pos = (q & 3) * 2 + (q >> 2);
    g_Wh[n * KDIM + blk * 16 + pos * 2 + (kk & 1)] = __float2half_rn(v);
}

// ---------------- main kernel ----------------
__global__ __launch_bounds__(THREADS, 1)
void sdt_fp16_kernel(const float* __restrict__ x,
                     const float* __restrict__ b1,
                     const float* __restrict__ W2,
                     const float* __restrict__ b2,
                     const float* __restrict__ leaf,
                     float* __restrict__ out)
{
    extern __shared__ char smem[];
    const uint32_t sbase = smem_u32_of(smem);
    float* b1s    = (float*)(smem + OFF_B1);
    float* W2s    = (float*)(smem + OFF_W2);
    float* b2s    = (float*)(smem + OFF_B2);
    float* leafs  = (float*)(smem + OFF_LEAF);
    float* rowsum = (float*)(smem + OFF_RS);

    const int tid  = threadIdx.x;
    const int lane = tid & 31;
    const int wid  = tid >> 5;
    const int wm   = wid & 1;
    const int wn   = wid >> 1;
    const int g    = lane >> 2;
    const int t4   = lane & 3;
    const int rowbase = blockIdx.x * M_CTA;

    // ---- prologue: W chunk 0 cp.async (group 0) ----
    #pragma unroll
    for (int it = 0; it < 8; it++) {
        int idx = tid + it * 384;           // 0..3071
        int row = idx >> 3, v = idx & 7;
        cp_async16(sbase + OFF_W0 + row * WPITCH + v * 16,
                   g_Wh + row * KDIM + v * 8);
    }
    asm volatile("cp.async.commit_group;" ::: "memory");

    // small tensors for the 6 live nodes
    for (int i = tid; i < NTOT; i += THREADS) {
        int node = i >> 6, h = i & 63;
        int gl = ((1 << node) - 1) * 64 + h;
        b1s[i] = b1[gl];
        W2s[i] = W2[gl];
    }
    if (tid < 6)  b2s[tid]   = b2[(1 << tid) - 1];
    if (tid < 64) leafs[tid] = leaf[tid];

    // ---- stage X (all 128 k), fp32 -> fp16, k-pair interleaved ----
    {
        const float4* xg = (const float4*)x;
        #pragma unroll
        for (int it = 0; it < 11; it++) {
            int idx = tid + it * 384;       // 0..4095
            if (idx < 4096) {
                int row = idx >> 5;         // 32 float4 per row
                int c4  = idx & 31;
                float4 v = xg[(size_t)(rowbase + row) * 32 + c4];
                __half2 h01 = __floats2half2_rn(v.x, v.y);
                __half2 h23 = __floats2half2_rn(v.z, v.w);
                int blk = c4 >> 2, m = c4 & 3;
                int pos_a = (m & 1) * 4 + (m >> 1);      // pair q=2c4
                uint32_t a = sbase + OFF_X + row * XPITCH + blk * 32 + pos_a * 4;
                sts32(a,     *(uint32_t*)&h01);
                sts32(a + 8, *(uint32_t*)&h23);          // pair q=2c4+1 -> pos_a+2
            }
        }
    }

    // ---- W chunk 1 cp.async (group 1) ----
    #pragma unroll
    for (int it = 0; it < 8; it++) {
        int idx = tid + it * 384;
        int row = idx >> 3, v = idx & 7;
        cp_async16(sbase + OFF_W1 + row * WPITCH + v * 16,
                   g_Wh + row * KDIM + 64 + v * 8);
    }
    asm volatile("cp.async.commit_group;" ::: "memory");

    float acc[4][8][4];
    #pragma unroll
    for (int mt = 0; mt < 4; mt++)
        #pragma unroll
        for (int nt = 0; nt < 8; nt++)
            #pragma unroll
            for (int j = 0; j < 4; j++) acc[mt][nt][j] = 0.0f;

    const uint32_t xb = sbase + OFF_X + (uint32_t)((wm * 64 + g) * XPITCH + t4 * 8);
    const uint32_t wrow = (uint32_t)((wn * 64 + g) * WPITCH + t4 * 8);

    // ---- chunk 0: k 0..63 ----
    asm volatile("cp.async.wait_group 1;" ::: "memory");
    __syncthreads();
    {
        const uint32_t wb = sbase + OFF_W0 + wrow;
        #pragma unroll
        for (int ks = 0; ks < 4; ks++) {
            const uint32_t ko = (uint32_t)(ks * 32);
            uint32_t A[4][4];
            #pragma unroll
            for (int mt = 0; mt < 4; mt++) {
                lds64(A[mt][0], A[mt][2], xb + (uint32_t)(mt * 16 * XPITCH) + ko);
                lds64(A[mt][1], A[mt][3], xb + (uint32_t)(mt * 16 * XPITCH) + 8 * XPITCH + ko);
            }
            #pragma unroll
            for (int nt = 0; nt < 8; nt++) {
                uint32_t b0, b1v_;
                lds64(b0, b1v_, wb + (uint32_t)(nt * 8 * WPITCH) + ko);
                #pragma unroll
                for (int mt = 0; mt < 4; mt++)
                    mma_fp16(acc[mt][nt], A[mt], b0, b1v_);
            }
        }
    }

    // ---- chunk 1: k 64..127 ----
    asm volatile("cp.async.wait_group 0;" ::: "memory");
    __syncthreads();
    {
        const uint32_t wb = sbase + OFF_W1 + wrow;
        #pragma unroll
        for (int ks = 0; ks < 4; ks++) {
            const uint32_t ko = (uint32_t)(ks * 32);
            const uint32_t xo = (uint32_t)((ks + 4) * 32);
            uint32_t A[4][4];
            #pragma unroll
            for (int mt = 0; mt < 4; mt++) {
                lds64(A[mt][0], A[mt][2], xb + (uint32_t)(mt * 16 * XPITCH) + xo);
                lds64(A[mt][1], A[mt][3], xb + (uint32_t)(mt * 16 * XPITCH) + 8 * XPITCH + xo);
            }
            #pragma unroll
            for (int nt = 0; nt < 8; nt++) {
                uint32_t b0, b1v_;
                lds64(b0, b1v_, wb + (uint32_t)(nt * 8 * WPITCH) + ko);
                #pragma unroll
                for (int mt = 0; mt < 4; mt++)
                    mma_fp16(acc[mt][nt], A[mt], b0, b1v_);
            }
        }
    }

    // ---- fused epilogue ----
    float b1v[16], W2v[16];
    #pragma unroll
    for (int nt = 0; nt < 8; nt++) {
        int col = wn * 64 + nt * 8 + t4 * 2;
        b1v[2 * nt]     = b1s[col];
        b1v[2 * nt + 1] = b1s[col + 1];
        W2v[2 * nt]     = W2s[col];
        W2v[2 * nt + 1] = W2s[col + 1];
    }
    __syncthreads();

    #pragma unroll
    for (int mt = 0; mt < 4; mt++) {
        float s0 = 0.0f, s1 = 0.0f;
        #pragma unroll
        for (int nt = 0; nt < 8; nt++) {
            s0 = fmaf(fmaxf(acc[mt][nt][0] + b1v[2 * nt], 0.0f),     W2v[2 * nt], s0);
            s0 = fmaf(fmaxf(acc[mt][nt][1] + b1v[2 * nt + 1], 0.0f), W2v[2 * nt + 1], s0);
            s1 = fmaf(fmaxf(acc[mt][nt][2] + b1v[2 * nt], 0.0f),     W2v[2 * nt], s1);
            s1 = fmaf(fmaxf(acc[mt][nt][3] + b1v[2 * nt + 1], 0.0f), W2v[2 * nt + 1], s1);
        }
        s0 += __shfl_xor_sync(0xffffffffu, s0, 1);
        s0 += __shfl_xor_sync(0xffffffffu, s0, 2);
        s1 += __shfl_xor_sync(0xffffffffu, s1, 1);
        s1 += __shfl_xor_sync(0xffffffffu, s1, 2);
        if (t4 == 0) {
            int r = wm * 64 + mt * 16 + g;
            rowsum[wn * 132 + r]     = s0;
            rowsum[wn * 132 + r + 8] = s1;
        }
    }
    __syncthreads();

    if (tid < M_CTA) {
        float p[6];
        #pragma unroll
        for (int k = 0; k < 6; k++) {
            float z = rowsum[k * 132 + tid] + b2s[k];
            p[k] = 1.0f / (1.0f + __expf(-z));
        }
        float v[32];
        #pragma unroll
        for (int m = 0; m < 32; m++)
            v[m] = fmaf(p[0], leafs[2 * m + 1], (1.0f - p[0]) * leafs[2 * m]);
        #pragma unroll
        for (int k = 1; k < 6; k++) {
            int len = 32 >> k;
            #pragma unroll
            for (int m = 0; m < 32; m++)
                if (m < len)
                    v[m] = fmaf(p[k], v[2 * m + 1], (1.0f - p[k]) * v[2 * m]);
        }
        out[rowbase + tid] = v[0];
    }
}

// ---------------- launch ----------------
extern "C" void kernel_launch(void* const* d_in, const int* in_sizes, int n_in,
                              void* d_out, int out_size)
{
    const float* x    = (const float*)d_in[0];
    const float* W1   = (const float*)d_in[1];
    const float* b1   = (const float*)d_in[2];
    const float* W2   = (const float*)d_in[3];
    const float* b2   = (const float*)d_in[4];
    const float* leaf = (const float*)d_in[5];
    float* out = (float*)d_out;

    cudaFuncSetAttribute(sdt_fp16_kernel, cudaFuncAttributeMaxDynamicSharedMemorySize, SMEM_BYTES);

    convert_w1_kernel<<<(NTOT * KDIM + 255) / 256, 256>>>(W1);
    sdt_fp16_kernel<<<NCTAS, THREADS, SMEM_BYTES>>>(x, b1, W2, b2, leaf, out);
}